// round 2
// baseline (speedup 1.0000x reference)
#include <cuda_runtime.h>

#define D    128
#define BM   128
#define BN   64
#define PAD  132   // padded row pitch in floats (16B aligned, conflict-friendly)

// scratch (no allocation allowed in kernel_launch)
__device__ float  g_sc[4096];
__device__ int    g_idx[65536];
__device__ double g_loss;

// ---------------------------------------------------------------------------
// Kernel 1: per-code squared norms  s_c[k] = sum_d c[k][d]^2  (fp32), zero loss
// ---------------------------------------------------------------------------
__global__ void k1_sc(const float* __restrict__ cb, int K) {
    int k = blockIdx.x * blockDim.x + threadIdx.x;
    if (k == 0 && blockIdx.x == 0) g_loss = 0.0;
    if (k < K) {
        const float* c = cb + (size_t)k * D;
        float s = 0.f;
        #pragma unroll 8
        for (int d = 0; d < D; d++) s += c[d] * c[d];
        g_sc[k] = s;
    }
}

// ---------------------------------------------------------------------------
// Kernel 2: fused distance-GEMM + argmin.
// Block: 128 tokens. Loop over codes in chunks of 64.
// Thread (ty,tx) of 16x16 grid owns 8 tokens x 4 codes.
// dist = fl( fl(s_z + s_c[k]) - 2*dot )  -- replicates reference fp32 sequence
// (2*dot is exact, so the FFMA contraction is bit-identical to mul+sub).
// ---------------------------------------------------------------------------
extern __shared__ float smem[];

__global__ __launch_bounds__(256, 2)
void k2_argmin(const float* __restrict__ z, const float* __restrict__ cb,
               float* __restrict__ out, int N, int K) {
    float* zs  = smem;                  // BM * PAD
    float* cbs = smem + BM * PAD;       // BN * PAD
    float* szs = cbs + BN * PAD;        // BM

    const int tid   = threadIdx.x;
    const int mbase = blockIdx.x * BM;

    // load z tile [BM x D] (coalesced, conflict-free float4 stores)
    for (int i = tid; i < BM * (D / 4); i += 256) {
        int m  = i / (D / 4);
        int d4 = i % (D / 4);
        float4 v = *(const float4*)(z + (size_t)(mbase + m) * D + d4 * 4);
        *(float4*)(zs + m * PAD + d4 * 4) = v;
    }
    __syncthreads();

    // per-token squared norm (fp32 — summation order is argmin-invariant)
    if (tid < BM) {
        const float* row = zs + tid * PAD;
        float s = 0.f;
        #pragma unroll 8
        for (int d = 0; d < D; d++) s += row[d] * row[d];
        szs[tid] = s;
    }
    __syncthreads();

    const int ty = tid >> 4;
    const int tx = tid & 15;
    const int m0 = ty * 8;

    float bestv[8];
    int   besti[8];
    #pragma unroll
    for (int r = 0; r < 8; r++) { bestv[r] = 3.4e38f; besti[r] = 0; }

    for (int kb = 0; kb < K; kb += BN) {
        // load codebook chunk [BN x D]
        for (int i = tid; i < BN * (D / 4); i += 256) {
            int n  = i / (D / 4);
            int d4 = i % (D / 4);
            float4 v = *(const float4*)(cb + (size_t)(kb + n) * D + d4 * 4);
            *(float4*)(cbs + n * PAD + d4 * 4) = v;
        }
        __syncthreads();

        float acc[8][4];
        #pragma unroll
        for (int r = 0; r < 8; r++)
            #pragma unroll
            for (int j = 0; j < 4; j++) acc[r][j] = 0.f;

        #pragma unroll 4
        for (int d = 0; d < D; d += 4) {
            float4 a[8], b[4];
            #pragma unroll
            for (int r = 0; r < 8; r++)
                a[r] = *(const float4*)(zs + (m0 + r) * PAD + d);
            #pragma unroll
            for (int j = 0; j < 4; j++)
                b[j] = *(const float4*)(cbs + (tx * 4 + j) * PAD + d);
            #pragma unroll
            for (int r = 0; r < 8; r++)
                #pragma unroll
                for (int j = 0; j < 4; j++) {
                    acc[r][j] += a[r].x * b[j].x;
                    acc[r][j] += a[r].y * b[j].y;
                    acc[r][j] += a[r].z * b[j].z;
                    acc[r][j] += a[r].w * b[j].w;
                }
        }

        // argmin update (ascending k within thread -> strict < keeps first min)
        #pragma unroll
        for (int r = 0; r < 8; r++) {
            float szv = szs[m0 + r];
            #pragma unroll
            for (int j = 0; j < 4; j++) {
                int   k    = kb + tx * 4 + j;
                float A    = szv + __ldg(&g_sc[k]);
                float dist = A - 2.0f * acc[r][j];
                if (dist < bestv[r]) { bestv[r] = dist; besti[r] = k; }
            }
        }
        __syncthreads();
    }

    // cross-tx reduction (reuse cbs region), tiebreak: min value then min index
    float* rv = cbs;                       // BM * 16 floats
    int*   ri = (int*)(cbs + BM * 16);     // BM * 16 ints (fits in BN*PAD)
    #pragma unroll
    for (int r = 0; r < 8; r++) {
        rv[(m0 + r) * 16 + tx] = bestv[r];
        ri[(m0 + r) * 16 + tx] = besti[r];
    }
    __syncthreads();

    if (tid < BM) {
        float bv = rv[tid * 16];
        int   bi = ri[tid * 16];
        #pragma unroll
        for (int t = 1; t < 16; t++) {
            float v  = rv[tid * 16 + t];
            int   i2 = ri[tid * 16 + t];
            if (v < bv || (v == bv && i2 < bi)) { bv = v; bi = i2; }
        }
        int tok = mbase + tid;
        g_idx[tok] = bi;
        out[(size_t)N * D + 1 + tok] = (float)bi;   // indices as float
    }
}

// ---------------------------------------------------------------------------
// Kernel 3: gather + straight-through output + loss partial sums
// z_q = fl(z + fl(q - z)) per element; loss term = fl((q-z)^2), summed in fp64
// ---------------------------------------------------------------------------
__global__ void k3_out(const float* __restrict__ z, const float* __restrict__ cb,
                       float* __restrict__ out, int ND) {
    __shared__ double warpsum[8];
    int e = blockIdx.x * 256 + threadIdx.x;
    double v = 0.0;
    if (e < ND) {
        int n = e >> 7;
        int d = e & 127;
        int idx = g_idx[n];
        float q  = cb[(size_t)idx * D + d];
        float zv = z[e];
        float t  = q - zv;        // fl(q - z)
        out[e]   = zv + t;        // fl(z + t)  (matches STE arithmetic)
        float sq = t * t;         // fl(t^2)
        v = (double)sq;
    }
    #pragma unroll
    for (int o = 16; o > 0; o >>= 1)
        v += __shfl_down_sync(0xffffffffu, v, o);
    if ((threadIdx.x & 31) == 0) warpsum[threadIdx.x >> 5] = v;
    __syncthreads();
    if (threadIdx.x == 0) {
        double s = 0.0;
        #pragma unroll
        for (int w = 0; w < 8; w++) s += warpsum[w];
        atomicAdd(&g_loss, s);
    }
}

// ---------------------------------------------------------------------------
// Kernel 4: finalize vq_loss = fl(m + fl(0.25*m)),  m = mean((q-z)^2)
// ---------------------------------------------------------------------------
__global__ void k4_loss(float* __restrict__ out, int ND) {
    if (threadIdx.x == 0 && blockIdx.x == 0) {
        double md = g_loss / (double)ND;
        float  m  = (float)md;
        out[ND] = m + 0.25f * m;
    }
}

// ---------------------------------------------------------------------------
extern "C" void kernel_launch(void* const* d_in, const int* in_sizes, int n_in,
                              void* d_out, int out_size) {
    const float* z  = (const float*)d_in[0];
    const float* cb = (const float*)d_in[1];
    float* out = (float*)d_out;

    int N = in_sizes[0] / D;   // 32768
    int K = in_sizes[1] / D;   // 1024
    int ND = N * D;

    const int SMEM = (BM * PAD + BN * PAD + BM) * (int)sizeof(float); // ~102 KB
    cudaFuncSetAttribute(k2_argmin, cudaFuncAttributeMaxDynamicSharedMemorySize, SMEM);

    k1_sc   <<<(K + 255) / 256, 256>>>(cb, K);
    k2_argmin<<<N / BM, 256, SMEM>>>(z, cb, out, N, K);
    k3_out  <<<(ND + 255) / 256, 256>>>(z, cb, out, ND);
    k4_loss <<<1, 32>>>(out, ND);
}

// round 5
// speedup vs baseline: 1.7537x; 1.7537x over previous
#include <cuda_runtime.h>
#include <cuda_bf16.h>
#include <cstdint>
#include <math.h>

#define D      128
#define NTOK   32768
#define KCODE  1024
#define TILEM  128
#define TILEN  128
#define NITER  8
#define PAD    132
#define Q      4

// ---------------- device scratch ----------------
__device__ __align__(16) __nv_bfloat16 g_zh[NTOK * D];
__device__ __align__(16) __nv_bfloat16 g_zl[NTOK * D];
__device__ __align__(16) __nv_bfloat16 g_ch[KCODE * D];
__device__ __align__(16) __nv_bfloat16 g_cl[KCODE * D];
__device__ float  g_sz[NTOK];
__device__ float  g_sc[KCODE];
__device__ int    g_idx[NTOK];
__device__ int    g_cand[NTOK * 16];
__device__ int    g_fixlist[NTOK];
__device__ int    g_nfix;
__device__ double g_loss;

// ---------------- helpers ----------------
__device__ __forceinline__ uint32_t smem_u32(const void* p) {
    uint32_t a;
    asm("{ .reg .u64 t; cvta.to.shared.u64 t, %1; cvt.u32.u64 %0, t; }" : "=r"(a) : "l"(p));
    return a;
}
__device__ __forceinline__ void ldsm_x4(uint32_t* r, uint32_t a) {
    asm volatile("ldmatrix.sync.aligned.m8n8.x4.shared.b16 {%0,%1,%2,%3}, [%4];"
                 : "=r"(r[0]), "=r"(r[1]), "=r"(r[2]), "=r"(r[3]) : "r"(a));
}
__device__ __forceinline__ void ldsm_x2(uint32_t* r, uint32_t a) {
    asm volatile("ldmatrix.sync.aligned.m8n8.x2.shared.b16 {%0,%1}, [%2];"
                 : "=r"(r[0]), "=r"(r[1]) : "r"(a));
}
__device__ __forceinline__ void mma16816(float* d, const uint32_t* a, const uint32_t* b) {
    asm volatile("mma.sync.aligned.m16n8k16.row.col.f32.bf16.bf16.f32 "
                 "{%0,%1,%2,%3},{%4,%5,%6,%7},{%8,%9},{%0,%1,%2,%3};"
                 : "+f"(d[0]), "+f"(d[1]), "+f"(d[2]), "+f"(d[3])
                 : "r"(a[0]), "r"(a[1]), "r"(a[2]), "r"(a[3]), "r"(b[0]), "r"(b[1]));
}
__device__ __forceinline__ void cp16(uint32_t dst, const void* src) {
    asm volatile("cp.async.cg.shared.global [%0], [%1], 16;" :: "r"(dst), "l"(src));
}
__device__ __forceinline__ void ins4(float (&v)[4], int (&ix)[4], float dd, int k) {
    if (dd < v[3]) {
        v[3] = dd; ix[3] = k;
        if (v[3] < v[2]) {
            float t = v[3]; v[3] = v[2]; v[2] = t; int ti = ix[3]; ix[3] = ix[2]; ix[2] = ti;
            if (v[2] < v[1]) {
                t = v[2]; v[2] = v[1]; v[1] = t; ti = ix[2]; ix[2] = ix[1]; ix[1] = ti;
                if (v[1] < v[0]) {
                    t = v[1]; v[1] = v[0]; v[0] = t; ti = ix[1]; ix[1] = ix[0]; ix[0] = ti;
                }
            }
        }
    }
}

// ---------------------------------------------------------------------------
// Prep: codebook norms (round-1-identical serial chain) + bf16 hi/lo split
// ---------------------------------------------------------------------------
__global__ void k_prep_c(const float* __restrict__ cb) {
    int k = blockIdx.x * blockDim.x + threadIdx.x;
    if (k == 0 && blockIdx.x == 0) { g_loss = 0.0; g_nfix = 0; }
    if (k < KCODE) {
        const float* c = cb + (size_t)k * D;
        float s = 0.f;
        #pragma unroll 8
        for (int d = 0; d < D; d++) {
            float x = c[d];
            s += x * x;
            __nv_bfloat16 xh = __float2bfloat16(x);
            float r = x - __bfloat162float(xh);
            g_ch[k * D + d] = xh;
            g_cl[k * D + d] = __float2bfloat16(r);
        }
        g_sc[k] = s;
    }
}

// ---------------------------------------------------------------------------
// Prep: token norms (round-1-identical serial chain) + bf16 hi/lo split
// ---------------------------------------------------------------------------
__global__ __launch_bounds__(256)
void k_prep_z(const float* __restrict__ z) {
    extern __shared__ float zsm[];
    int tid = threadIdx.x;
    int mbase = blockIdx.x * 128;
    for (int i = tid; i < 128 * (D / 4); i += 256) {
        int m = i / (D / 4), d4 = i % (D / 4);
        float4 v = *(const float4*)(z + (size_t)(mbase + m) * D + d4 * 4);
        *(float4*)(zsm + m * PAD + d4 * 4) = v;
    }
    __syncthreads();
    if (tid < 128) {
        const float* row = zsm + tid * PAD;
        float s = 0.f;
        #pragma unroll 8
        for (int d = 0; d < D; d++) s += row[d] * row[d];
        g_sz[mbase + tid] = s;
    }
    for (int i = tid; i < 128 * D; i += 256) {
        int m = i >> 7, d = i & 127;
        float x = zsm[m * PAD + d];
        __nv_bfloat16 xh = __float2bfloat16(x);
        float r = x - __bfloat162float(xh);
        size_t e = (size_t)(mbase + m) * D + d;
        g_zh[e] = xh;
        g_zl[e] = __float2bfloat16(r);
    }
}

// ---------------------------------------------------------------------------
// Main: HMMA bf16 hi/lo-split distance GEMM + top-4 margin epilogue
// SMEM: [sc 4KB][A hi 32KB][A lo 32KB][B dbuf 2x(hi32+lo32)KB] = 196KB
// swizzle: 16B chunk c of row r at  r*256 + ((c ^ (r&7))<<4)
// ---------------------------------------------------------------------------
#define SM_SC 0
#define SM_A  4096
#define SM_B  69632
#define SM_TOT 200704

extern __shared__ char smem[];

__global__ __launch_bounds__(256, 1) void k_mma() {
    uint32_t sb = smem_u32(smem);
    int tid = threadIdx.x, wid = tid >> 5, lane = tid & 31;
    int mbase = blockIdx.x * TILEM;
    int wrow = wid * 16;

    for (int i = tid; i < KCODE; i += 256) ((float*)smem)[i] = g_sc[i];

    // A tiles (hi/lo), swizzled
    for (int i = tid; i < 2048; i += 256) {
        int row = i >> 4, c = i & 15;
        uint32_t doff = SM_A + row * 256 + ((c ^ (row & 7)) << 4);
        size_t srow = (size_t)(mbase + row) * 256 + c * 16;
        *(uint4*)(smem + doff)         = *(const uint4*)((const char*)g_zh + srow);
        *(uint4*)(smem + doff + 32768) = *(const uint4*)((const char*)g_zl + srow);
    }
    // prefetch B tile 0
    for (int i = tid; i < 2048; i += 256) {
        int row = i >> 4, c = i & 15;
        uint32_t doff = SM_B + row * 256 + ((c ^ (row & 7)) << 4);
        size_t srow = (size_t)row * 256 + c * 16;
        cp16(sb + doff,         (const char*)g_ch + srow);
        cp16(sb + doff + 32768, (const char*)g_cl + srow);
    }
    asm volatile("cp.async.commit_group;");

    int r0 = wrow + (lane >> 2), r1 = r0 + 8;
    float sz0 = g_sz[mbase + r0], sz1 = g_sz[mbase + r1];

    float tv0[Q], tv1[Q]; int ti0[Q], ti1[Q];
    #pragma unroll
    for (int q = 0; q < Q; q++) {
        tv0[q] = 3.4e38f; tv1[q] = 3.4e38f; ti0[q] = 0x7fffffff; ti1[q] = 0x7fffffff;
    }

    for (int it = 0; it < NITER; it++) {
        if (it + 1 < NITER) {
            int code0 = (it + 1) * TILEN;
            uint32_t bb = SM_B + ((it + 1) & 1) * 65536;
            for (int i = tid; i < 2048; i += 256) {
                int row = i >> 4, c = i & 15;
                uint32_t doff = bb + row * 256 + ((c ^ (row & 7)) << 4);
                size_t srow = (size_t)(code0 + row) * 256 + c * 16;
                cp16(sb + doff,         (const char*)g_ch + srow);
                cp16(sb + doff + 32768, (const char*)g_cl + srow);
            }
            asm volatile("cp.async.commit_group;");
            asm volatile("cp.async.wait_group 1;");
        } else {
            asm volatile("cp.async.wait_group 0;");
        }
        __syncthreads();

        float acc[16][4];
        #pragma unroll
        for (int nt = 0; nt < 16; nt++)
            #pragma unroll
            for (int j = 0; j < 4; j++) acc[nt][j] = 0.f;

        uint32_t bbase = sb + SM_B + (it & 1) * 65536;
        int rowA = wrow + (lane & 15);
        uint32_t abase = sb + SM_A + rowA * 256;

        #pragma unroll
        for (int ks = 0; ks < 8; ks++) {
            uint32_t ah[4], al[4];
            int cA = ks * 2 + (lane >> 4);
            uint32_t aaddr = abase + ((cA ^ (rowA & 7)) << 4);
            ldsm_x4(ah, aaddr);
            ldsm_x4(al, aaddr + 32768);
            #pragma unroll
            for (int nt = 0; nt < 16; nt++) {
                int rowB = nt * 8 + (lane & 7);
                int cB = ks * 2 + ((lane >> 3) & 1);
                uint32_t baddr = bbase + rowB * 256 + ((cB ^ (rowB & 7)) << 4);
                uint32_t bh[2], bl[2];
                ldsm_x2(bh, baddr);
                ldsm_x2(bl, baddr + 32768);
                mma16816(acc[nt], ah, bh);
                mma16816(acc[nt], ah, bl);
                mma16816(acc[nt], al, bh);
            }
        }

        // epilogue: dd = fl(fl(sz+sc) - 2*acc), top-4 per row
        const float* scs = (const float*)smem;
        #pragma unroll
        for (int nt = 0; nt < 16; nt++) {
            int col = it * TILEN + nt * 8 + 2 * (lane & 3);
            float s0 = scs[col], s1 = scs[col + 1];
            float dd;
            dd = (sz0 + s0) - 2.0f * acc[nt][0]; ins4(tv0, ti0, dd, col);
            dd = (sz0 + s1) - 2.0f * acc[nt][1]; ins4(tv0, ti0, dd, col + 1);
            dd = (sz1 + s0) - 2.0f * acc[nt][2]; ins4(tv1, ti1, dd, col);
            dd = (sz1 + s1) - 2.0f * acc[nt][3]; ins4(tv1, ti1, dd, col + 1);
        }
        __syncthreads();
    }

    // merge per token (scratch aliases B buffer 0)
    float* sv = (float*)(smem + SM_B);
    int*   si = (int*)(smem + SM_B + 8192);
    int lg = lane & 3;
    #pragma unroll
    for (int q = 0; q < Q; q++) {
        sv[r0 * 16 + lg * 4 + q] = tv0[q]; si[r0 * 16 + lg * 4 + q] = ti0[q];
        sv[r1 * 16 + lg * 4 + q] = tv1[q]; si[r1 * 16 + lg * 4 + q] = ti1[q];
    }
    __syncthreads();

    if (tid < 128) {
        int row = tid, tok = mbase + row, base = row * 16;
        float bv = 3.4e38f; int bi = 0x7fffffff;
        #pragma unroll
        for (int e = 0; e < 16; e++) {
            float v = sv[base + e]; int ii = si[base + e];
            if (v < bv || (v == bv && ii < bi)) { bv = v; bi = ii; }
        }
        float ge = exp2f((float)(ilogbf(fmaxf(fabsf(bv), 1e-20f)) - 23));
        float th = bv + 2.0f * ge + 3e-5f;
        int full = 0, cnt = 0;
        #pragma unroll
        for (int l = 0; l < 4; l++)
            if (sv[base + l * 4 + (Q - 1)] <= th) full = 1;  // lane list may overflow
        #pragma unroll
        for (int e = 0; e < 16; e++)
            if (sv[base + e] <= th) { g_cand[tok * 16 + cnt] = si[base + e]; cnt++; }
        if (cnt <= 1 && !full) {
            g_idx[tok] = bi;
        } else {
            int pos = atomicAdd(&g_nfix, 1);
            g_fixlist[pos] = tok | (cnt << 16) | (full << 31);
        }
    }
}

// ---------------------------------------------------------------------------
// Fixup: exact fp32 reference-sequence distances (serial FFMA chain, the
// arithmetic validated bit-for-bit in round 2) for flagged tokens.
// ---------------------------------------------------------------------------
__global__ __launch_bounds__(256)
void k_fix(const float* __restrict__ z, const float* __restrict__ cb) {
    int gw = (blockIdx.x * 256 + threadIdx.x) >> 5;
    int lane = threadIdx.x & 31;
    int nw = (gridDim.x * 256) >> 5;
    int nf = g_nfix;
    for (int i = gw; i < nf; i += nw) {
        int e = g_fixlist[i];
        int tok = e & 0xffff;
        int cnt = (e >> 16) & 0x1f;
        int full = (e >> 31) & 1;
        float sz = g_sz[tok];
        const float* zr = z + (size_t)tok * D;
        float bv = 3.4e38f; int bi = 0x7fffffff;
        if (!full) {
            if (lane < cnt) {
                int k = g_cand[tok * 16 + lane];
                const float* cr = cb + (size_t)k * D;
                float p = 0.f;
                #pragma unroll 8
                for (int d = 0; d < D; d++) p += zr[d] * cr[d];
                bv = (sz + g_sc[k]) - 2.0f * p;
                bi = k;
            }
        } else {
            for (int k = lane; k < KCODE; k += 32) {
                const float* cr = cb + (size_t)k * D;
                float p = 0.f;
                #pragma unroll 8
                for (int d = 0; d < D; d++) p += zr[d] * cr[d];
                float dd = (sz + g_sc[k]) - 2.0f * p;
                if (dd < bv || (dd == bv && k < bi)) { bv = dd; bi = k; }
            }
        }
        #pragma unroll
        for (int o = 16; o > 0; o >>= 1) {
            float ov = __shfl_down_sync(~0u, bv, o);
            int   oi = __shfl_down_sync(~0u, bi, o);
            if (ov < bv || (ov == bv && oi < bi)) { bv = ov; bi = oi; }
        }
        if (lane == 0) g_idx[tok] = bi;
    }
}

// ---------------------------------------------------------------------------
// Output: gather + STE + loss partials + index slots
// ---------------------------------------------------------------------------
__global__ void k_out(const float* __restrict__ z, const float* __restrict__ cb,
                      float* __restrict__ out, int ND) {
    __shared__ double warpsum[8];
    int e = blockIdx.x * 256 + threadIdx.x;
    double v = 0.0;
    if (e < ND) {
        int n = e >> 7, d = e & 127;
        int idx = g_idx[n];
        float q = cb[(size_t)idx * D + d];
        float zv = z[e];
        float t = q - zv;
        out[e] = zv + t;
        v = (double)(t * t);
        if (d == 0) out[(size_t)ND + 1 + n] = (float)idx;
    }
    #pragma unroll
    for (int o = 16; o > 0; o >>= 1) v += __shfl_down_sync(0xffffffffu, v, o);
    if ((threadIdx.x & 31) == 0) warpsum[threadIdx.x >> 5] = v;
    __syncthreads();
    if (threadIdx.x == 0) {
        double s = 0.0;
        #pragma unroll
        for (int w = 0; w < 8; w++) s += warpsum[w];
        atomicAdd(&g_loss, s);
    }
}

__global__ void k_final(float* __restrict__ out, int ND) {
    if (threadIdx.x == 0 && blockIdx.x == 0) {
        double md = g_loss / (double)ND;
        float m = (float)md;
        out[ND] = m + 0.25f * m;
    }
}

// ---------------------------------------------------------------------------
extern "C" void kernel_launch(void* const* d_in, const int* in_sizes, int n_in,
                              void* d_out, int out_size) {
    const float* z  = (const float*)d_in[0];
    const float* cb = (const float*)d_in[1];
    float* out = (float*)d_out;

    int N = in_sizes[0] / D;
    int K = in_sizes[1] / D;
    int ND = N * D;

    cudaFuncSetAttribute(k_prep_z, cudaFuncAttributeMaxDynamicSharedMemorySize,
                         128 * PAD * (int)sizeof(float));
    cudaFuncSetAttribute(k_mma, cudaFuncAttributeMaxDynamicSharedMemorySize, SM_TOT);

    k_prep_c<<<(K + 255) / 256, 256>>>(cb);
    k_prep_z<<<N / 128, 256, 128 * PAD * sizeof(float)>>>(z);
    k_mma   <<<N / TILEM, 256, SM_TOT>>>();
    k_fix   <<<64, 256>>>(z, cb);
    k_out   <<<(ND + 255) / 256, 256>>>(z, cb, out, ND);
    k_final <<<1, 32>>>(out, ND);
}